// round 16
// baseline (speedup 1.0000x reference)
#include <cuda_runtime.h>
#include <cuda_bf16.h>
#include <math.h>
#include <stdint.h>

#define SS 16
#define NN 4096
#define MM 128
#define DD 128
#define OO 128
#define PAD 129

__device__ float g_w[SS*OO*DD];
__device__ float g_klso[SS*OO];

// ---- smem layout (byte offsets). P/SB alias A (time-disjoint). ----
#define OFF_A      0        // float Af[128*129] = 66048 B
#define OFF_P      0        // float P[64][129] = 33024 B (aliases A)
#define OFF_SB0    33024    // bf16 staging [128][272B] = 34816 B (aliases A tail + 1.8KB)
#define OFF_DV     67840    // Dinv block 16x17 floats = 1088 B
#define OFF_SQLP   68928
#define OFF_SMU    69440
#define OFF_UTLV   69952
#define OFF_DINV   70464
#define OFF_TF     70976
#define OFF_EPSV   71488
#define OFF_RED    72000
#define SMEM_DYN   72512

#define SB_STRIDE_B 272     // 64 m-pairs * 4B + 16B pad
#define P_STRIDE    129

__device__ __forceinline__ uint32_t s2u(const void* p) {
    uint32_t a;
    asm("{ .reg .u64 t; cvta.to.shared.u64 t, %1; cvt.u32.u64 %0, t; }"
        : "=r"(a) : "l"(p));
    return a;
}

__device__ __forceinline__ void ldsm_x4(uint32_t addr, uint32_t& r0, uint32_t& r1,
                                        uint32_t& r2, uint32_t& r3) {
    asm volatile("ldmatrix.sync.aligned.m8n8.x4.shared.b16 {%0,%1,%2,%3}, [%4];"
                 : "=r"(r0), "=r"(r1), "=r"(r2), "=r"(r3) : "r"(addr));
}

__device__ __forceinline__ void mma16816(float& c0, float& c1, float& c2, float& c3,
                                         uint32_t a0, uint32_t a1, uint32_t a2, uint32_t a3,
                                         uint32_t b0, uint32_t b1) {
    asm volatile(
        "mma.sync.aligned.m16n8k16.row.col.f32.bf16.bf16.f32 "
        "{%0,%1,%2,%3}, {%4,%5,%6,%7}, {%8,%9}, {%0,%1,%2,%3};"
        : "+f"(c0), "+f"(c1), "+f"(c2), "+f"(c3)
        : "r"(a0), "r"(a1), "r"(a2), "r"(a3), "r"(b0), "r"(b1));
}

__device__ __forceinline__ uint32_t pack_bf2(__nv_bfloat16 lo, __nv_bfloat16 hi) {
    uint16_t a = __bfloat16_as_ushort(lo), b = __bfloat16_as_ushort(hi);
    return (uint32_t)a | ((uint32_t)b << 16);
}
__device__ __forceinline__ uint32_t swap16(uint32_t x) {
    return __byte_perm(x, x, 0x1032);
}

// ---- 32x32 warp Cholesky (all 32 lanes of warp 0; lane = row) ----
__device__ __forceinline__ void chol32_warp(float* A, float* dinv) {
    const int lane = threadIdx.x & 31;
    float row[32];
#pragma unroll
    for (int k = 0; k < 32; k++) row[k] = A[lane*PAD + k];
#pragma unroll
    for (int j = 0; j < 32; j++) {
        float raw = __shfl_sync(0xFFFFFFFFu, row[j], j);
        float inv = __fdividef(1.0f, raw);
        float tj = row[j] * inv;
#pragma unroll
        for (int k = j + 1; k < 32; k++) {
            float rkj = __shfl_sync(0xFFFFFFFFu, row[j], k);
            row[k] = fmaf(-tj, rkj, row[k]);
        }
    }
    float rs_own = rsqrtf(row[lane]);      // lane's own raw diag survives
    float diagv  = row[lane] * rs_own;     // sqrt(raw)
#pragma unroll
    for (int k = 0; k < 32; k++) {
        float rsk = __shfl_sync(0xFFFFFFFFu, rs_own, k);
        float v = row[k] * rsk;
        if (k == lane) v = diagv;
        A[lane*PAD + k] = v;               // upper garbage, never read
    }
    dinv[lane] = rs_own;
    __syncwarp();
}

// Blocked (32-wide) in-place Cholesky; dinv[j] = 1/L[j][j]. Upper = garbage.
__device__ __noinline__ void chol_blocked(float* A, float* dinv, int tid) {
    const int warp = tid >> 5;
    const int ty = tid >> 4, tx = tid & 15;
#pragma unroll
    for (int jb = 0; jb < 4; jb++) {
        if (warp == 0) chol32_warp(A + (jb*32)*PAD + jb*32, dinv + jb*32);
        __syncthreads();
        const int nrows = 96 - jb*32;
        if (tid < nrows) {
            const int i = jb*32 + 32 + tid;
            const float* Ld = A + (jb*32)*PAD + jb*32;
            const float* dvp = dinv + jb*32;
            float* Ai = A + i*PAD + jb*32;
            float t[32];
#pragma unroll
            for (int j = 0; j < 32; j++) t[j] = Ai[j];
#pragma unroll
            for (int j = 0; j < 32; j++) {
                float v = t[j] * dvp[j];
                t[j] = v;
#pragma unroll
                for (int k = j + 1; k < 32; k++)
                    t[k] = fmaf(-v, Ld[k*PAD + j], t[k]);
            }
#pragma unroll
            for (int j = 0; j < 32; j++) Ai[j] = t[j];
        }
        __syncthreads();
        if (jb < 3) {
            float tacc[8][8];
#pragma unroll
            for (int a = 2*jb+2; a < 8; a++)
#pragma unroll
                for (int b = 2*jb+2; b <= a; b++) tacc[a][b] = 0.0f;
            float pa[8], pb[8];
#pragma unroll
            for (int k = 0; k < 32; k++) {
#pragma unroll
                for (int a = 2*jb+2; a < 8; a++) pa[a] = A[(ty + 16*a)*PAD + jb*32 + k];
#pragma unroll
                for (int b = 2*jb+2; b < 8; b++) pb[b] = A[(tx + 16*b)*PAD + jb*32 + k];
#pragma unroll
                for (int a = 2*jb+2; a < 8; a++)
#pragma unroll
                    for (int b = 2*jb+2; b <= a; b++) tacc[a][b] += pa[a] * pb[b];
            }
#pragma unroll
            for (int a = 2*jb+2; a < 8; a++)
#pragma unroll
                for (int b = 2*jb+2; b <= a; b++)
                    A[(ty + 16*a)*PAD + tx + 16*b] -= tacc[a][b];
            __syncthreads();
        }
    }
}

// Blocked X = L^{-1}, scratch-free in-place (proven R15 phase order).
__device__ __noinline__ void trsm_blocked(float* A, const float* dinv,
                                          float* Dv, int tid) {
    const int warp = tid >> 5;
    const int lane = tid & 31;
    const int c = lane & 15, rh = lane >> 4;
#pragma unroll
    for (int ib = 0; ib < 8; ib++) {
        if (warp == 7 && lane < 16) {
            const float* Ld = A + (ib*16)*PAD + ib*16;
            float dv[16], t[16];
#pragma unroll
            for (int r = 0; r < 16; r++) dv[r] = dinv[ib*16 + r];
#pragma unroll
            for (int r = 0; r < 16; r++) t[r] = (r == c) ? 1.0f : 0.0f;
#pragma unroll
            for (int r = 0; r < 16; r++) {
                float x = t[r] * dv[r];
                t[r] = x;
#pragma unroll
                for (int k = r + 1; k < 16; k++)
                    t[k] = fmaf(-x, Ld[k*PAD + r], t[k]);
            }
#pragma unroll
            for (int r = 0; r < 16; r++) Dv[r*17 + c] = t[r];
        }
        float acc[8];
        if (warp < ib) {
#pragma unroll
            for (int q = 0; q < 8; q++) acc[q] = 0.0f;
            for (int kb = warp; kb < ib; kb++) {
#pragma unroll
                for (int k = 0; k < 16; k++) {
                    float xv = A[(kb*16 + k)*PAD + warp*16 + c];
#pragma unroll
                    for (int q = 0; q < 8; q++)
                        acc[q] -= A[(ib*16 + rh*8 + q)*PAD + kb*16 + k] * xv;
                }
            }
        }
        __syncthreads();   // ALL reads of L row ib complete; Dv visible
        if (warp < ib) {
#pragma unroll
            for (int q = 0; q < 8; q++)
                A[(ib*16 + rh*8 + q)*PAD + warp*16 + c] = acc[q];
            __syncwarp();
            float tcol[16];
#pragma unroll
            for (int k = 0; k < 16; k++)
                tcol[k] = A[(ib*16 + k)*PAD + warp*16 + c];
            __syncwarp();
#pragma unroll
            for (int q = 0; q < 8; q++) {
                const int r = rh*8 + q;
                float t = 0.0f;
#pragma unroll
                for (int k = 0; k <= r; k++)
                    t = fmaf(Dv[r*17 + k], tcol[k], t);
                A[(ib*16 + r)*PAD + warp*16 + c] = t;
            }
        }
        if (warp == 7 && lane < 16) {
#pragma unroll
            for (int r = 0; r < 16; r++)
                A[(ib*16 + r)*PAD + ib*16 + c] = Dv[r*17 + c];
        }
        __syncthreads();
    }
}

__global__ __launch_bounds__(256, 3)
void k1_factor(const float* __restrict__ U,
               const float* __restrict__ pmu,
               const float* __restrict__ plogprec,
               const float* __restrict__ eps) {
    extern __shared__ unsigned char smraw[];
    char* sm = (char*)smraw;
    const uint32_t smb = s2u(sm);

    float* A    = (float*)(sm + OFF_A);
    float* P    = (float*)(sm + OFF_P);
    float* Dv   = (float*)(sm + OFF_DV);
    float* sqlp = (float*)(sm + OFF_SQLP);
    float* smu  = (float*)(sm + OFF_SMU);
    float* utlv = (float*)(sm + OFF_UTLV);
    float* dinv = (float*)(sm + OFF_DINV);
    float* tf   = (float*)(sm + OFF_TF);
    float* epsv = (float*)(sm + OFF_EPSV);
    float* red  = (float*)(sm + OFF_RED);

    const int so = blockIdx.x;
    const int s = so >> 7;
    const int o = so & 127;
    const int tid = threadIdx.x;
    const int wid = tid >> 5;
    const int lane = tid & 31;

    if (tid < 128) {
        float l = expf(plogprec[o*MM + tid]);
        float sq = sqrtf(l);
        sqlp[tid] = sq;
        smu[tid]  = sq * pmu[o*MM + tid];
        epsv[tid] = eps[(s*OO + o)*DD + tid];
        utlv[tid] = 0.0f;
    }
    __syncthreads();

    // ---- tile lists: 72 lower tiles, 9/warp, static fill ----
    int rbv[9], jbv[9];
#pragma unroll
    for (int t = 0; t < 9; t++) {
        int idx = wid + 8*t;
        int rb = (int)(0.5f * (sqrtf(4.0f*(float)idx + 1.0f) - 1.0f));
        if (rb*rb + rb > idx) rb--;
        if ((rb+1)*(rb+1) + (rb+1) <= idx) rb++;
        rbv[t] = rb;
        jbv[t] = idx - rb*rb - rb;
    }
    const int aRow  = lane & 15;
    const int aColH = (lane >> 4) * 8;
    const int bRow  = lane & 7;
    const int bCol  = (lane >> 3) * 8;

    float cc[9][4];
#pragma unroll
    for (int t = 0; t < 9; t++)
#pragma unroll
        for (int q = 0; q < 4; q++) cc[t][q] = 0.f;

    const int pfd = tid & 127;
    const int pfm = tid >> 7;

    // ============ Gram = P~^T P~  (2 x 64-m chunks; P/SB alias A) ============
#pragma unroll
    for (int c = 0; c < 2; c++) {
#pragma unroll
        for (int it = 0; it < 32; it++) {
            int ml = pfm + 2*it;
            float u = U[((size_t)s*MM + c*64 + ml)*DD + pfd];
            P[ml*P_STRIDE + pfd] = sqlp[c*64 + ml] * fmaxf(u, 0.f);
        }
        __syncthreads();
        if (tid < 128) {
            float a = utlv[tid];
#pragma unroll
            for (int ml = 0; ml < 64; ml++)
                a = fmaf(smu[c*64 + ml], P[ml*P_STRIDE + tid], a);
            utlv[tid] = a;
        }
#pragma unroll
        for (int it = 0; it < 32; it++) {
            int idx = tid + it*256;
            int ml = idx & 63, d = idx >> 6;
            float v = P[ml*P_STRIDE + d];
            __nv_bfloat16 h = __float2bfloat16(v);
            __nv_bfloat16 m2 = __float2bfloat16(v - __bfloat162float(h));
            *(uint32_t*)(sm + OFF_SB0 + d*SB_STRIDE_B + ml*4) = pack_bf2(h, m2);
        }
        __syncthreads();
#pragma unroll
        for (int t = 0; t < 9; t++) {
            uint32_t aBase = smb + OFF_SB0 + (uint32_t)(rbv[t]*16 + aRow)*SB_STRIDE_B + aColH*2;
            uint32_t bBase = smb + OFF_SB0 + (uint32_t)(jbv[t]*8 + bRow)*SB_STRIDE_B + bCol*2;
#pragma unroll
            for (int g = 0; g < 4; g++) {
                uint32_t b0,b1,b2,b3;
                ldsm_x4(bBase + g*64, b0,b1,b2,b3);
                uint32_t s0 = swap16(b0), s1 = swap16(b1), s2 = swap16(b2), s3 = swap16(b3);
                uint32_t a0,a1,a2,a3;
                ldsm_x4(aBase + (2*g)*32, a0,a1,a2,a3);
                mma16816(cc[t][0],cc[t][1],cc[t][2],cc[t][3], a0,a1,a2,a3, b0,b1);
                mma16816(cc[t][0],cc[t][1],cc[t][2],cc[t][3], a0,a1,a2,a3, s0,s1);
                ldsm_x4(aBase + (2*g+1)*32, a0,a1,a2,a3);
                mma16816(cc[t][0],cc[t][1],cc[t][2],cc[t][3], a0,a1,a2,a3, b2,b3);
                mma16816(cc[t][0],cc[t][1],cc[t][2],cc[t][3], a0,a1,a2,a3, s2,s3);
            }
        }
        __syncthreads();
    }
    // store Gram + I, FLIPPED: Af[127-j][127-i] = G[i][j]
    {
        const int g = lane >> 2, tc = (lane & 3) * 2;
#pragma unroll
        for (int t = 0; t < 9; t++) {
            int i0 = rbv[t]*16 + g, j0 = jbv[t]*8 + tc;
            A[(127-j0)*PAD + (127-i0)]     = cc[t][0] + (i0 == j0     ? 1.f : 0.f);
            A[(127-j0-1)*PAD + (127-i0)]   = cc[t][1] + (i0 == j0 + 1 ? 1.f : 0.f);
            A[(127-j0)*PAD + (127-i0-8)]   = cc[t][2] + (i0+8 == j0   ? 1.f : 0.f);
            A[(127-j0-1)*PAD + (127-i0-8)] = cc[t][3] + (i0+8 == j0+1 ? 1.f : 0.f);
        }
    }
    __syncthreads();

    // ---- Lf = chol(Af) (32-blocked); Xf = Lf^{-1} ----
    chol_blocked(A, dinv, tid);
    trsm_blocked(A, dinv, Dv, tid);

    // ---- tf = Xf @ flip(utlv) ----
    if (tid < 128) {
        const float* Ar = A + tid*PAD;
        float a = 0.f;
        for (int e = 0; e <= tid; e++)
            a = fmaf(Ar[e], utlv[127 - e], a);
        tf[tid] = a;
    }
    __syncthreads();

    // ---- column dots over column c=127-i: q_mu, Lcov@eps, colnorm ----
    if (tid < 128) {
        const int c = 127 - tid;
        float qm = 0.f, we = 0.f, ss = 0.f;
        for (int k = (c & ~15); k < 128; k++) {
            float x = A[k*PAD + c];
            qm = fmaf(x, tf[k], qm);
            we = fmaf(x, epsv[127 - k], we);
            ss = fmaf(x, x, ss);
        }
        g_w[(s*OO + o)*DD + tid] = qm + we;
        red[tid] = 0.5f*(ss + qm*qm) - logf(dinv[tid]);
    }
    __syncthreads();
    if (tid < 32) {
        float p = red[tid] + red[tid+32] + red[tid+64] + red[tid+96];
#pragma unroll
        for (int off = 16; off > 0; off >>= 1)
            p += __shfl_xor_sync(0xFFFFFFFFu, p, off);
        if (tid == 0)
            g_klso[so] = p - 64.0f;
    }
}

// ---- k2: F_out / U_out GEMMs, float4-over-k ----
#define KP 36
__global__ __launch_bounds__(256, 2)
void k2_gemm(const float* __restrict__ F, const float* __restrict__ U,
             float* __restrict__ outF, float* __restrict__ outU) {
    __shared__ float At[128*KP];
    __shared__ float Bt[128*KP];
    const int b = blockIdx.x;
    const int tid = threadIdx.x;
    const int ty = tid >> 4, tx = tid & 15;

    int s;
    const float* Ag;
    float* Cg;
    if (b < SS * (NN/128)) {
        s = b >> 5;
        int nt = b & 31;
        Ag = F + (size_t)(s*NN + nt*128) * DD;
        Cg = outF + (size_t)(s*NN + nt*128) * OO;
    } else {
        s = b - SS * (NN/128);
        Ag = U + (size_t)(s*MM) * DD;
        Cg = outU + (size_t)(s*MM) * OO;
    }
    const float* W = g_w + (size_t)s * OO * DD;

    float acc[8][8];
#pragma unroll
    for (int a = 0; a < 8; a++)
#pragma unroll
        for (int c = 0; c < 8; c++) acc[a][c] = 0.0f;

    for (int kb = 0; kb < DD; kb += 32) {
        __syncthreads();
        for (int idx = tid; idx < 128*8; idx += 256) {
            int r = idx >> 3, c4 = idx & 7;
            float4 v = *(const float4*)&Ag[r*DD + kb + 4*c4];
            v.x = fmaxf(v.x, 0.f); v.y = fmaxf(v.y, 0.f);
            v.z = fmaxf(v.z, 0.f); v.w = fmaxf(v.w, 0.f);
            *(float4*)&At[r*KP + 4*c4] = v;
            *(float4*)&Bt[r*KP + 4*c4] = *(const float4*)&W[r*DD + kb + 4*c4];
        }
        __syncthreads();
#pragma unroll
        for (int k4 = 0; k4 < 8; k4++) {
            float4 bv[8];
#pragma unroll
            for (int c = 0; c < 8; c++)
                bv[c] = *(const float4*)&Bt[(tx + 16*c)*KP + 4*k4];
#pragma unroll
            for (int a = 0; a < 8; a++) {
                float4 av = *(const float4*)&At[(ty + 16*a)*KP + 4*k4];
#pragma unroll
                for (int c = 0; c < 8; c++) {
                    acc[a][c] += av.x * bv[c].x;
                    acc[a][c] += av.y * bv[c].y;
                    acc[a][c] += av.z * bv[c].z;
                    acc[a][c] += av.w * bv[c].w;
                }
            }
        }
    }
#pragma unroll
    for (int a = 0; a < 8; a++)
#pragma unroll
        for (int c = 0; c < 8; c++)
            Cg[(ty + 16*a)*OO + tx + 16*c] = acc[a][c];
}

__global__ void k3_kl(float* __restrict__ kl) {
    int s = threadIdx.x;
    if (s < SS) {
        float a = 0.0f;
        for (int o = 0; o < OO; o++) a += g_klso[s*OO + o];
        kl[s] = a;
    }
}

extern "C" void kernel_launch(void* const* d_in, const int* in_sizes, int n_in,
                              void* d_out, int out_size) {
    const float* F        = (const float*)d_in[0];
    const float* U        = (const float*)d_in[1];
    const float* pmu      = (const float*)d_in[2];
    const float* plogprec = (const float*)d_in[3];
    const float* eps      = (const float*)d_in[4];

    float* out  = (float*)d_out;
    float* outF = out;
    float* outU = outF + (size_t)SS*NN*OO;
    float* outK = outU + (size_t)SS*MM*OO;

    cudaFuncSetAttribute(k1_factor, cudaFuncAttributeMaxDynamicSharedMemorySize,
                         SMEM_DYN);

    k1_factor<<<SS*OO, 256, SMEM_DYN>>>(U, pmu, plogprec, eps);
    k2_gemm<<<SS*(NN/128) + SS, 256>>>(F, U, outF, outU);
    k3_kl<<<1, 32>>>(outK);
}

// round 17
// speedup vs baseline: 1.0552x; 1.0552x over previous
#include <cuda_runtime.h>
#include <cuda_bf16.h>
#include <math.h>
#include <stdint.h>

#define SS 16
#define NN 4096
#define MM 128
#define DD 128
#define OO 128
#define PAD 129

__device__ float g_w[SS*OO*DD];
__device__ float g_klso[SS*OO];

// ---- smem layout (byte offsets) ----
#define OFF_A      0        // float Af[128*129] = 66048 B (SB0/P alias here during Gram)
#define OFF_SB0    0        // bf16 staging [128][72] = 18432 B (aliases A)
#define OFF_P      18432    // float P[32][129] = 16512 B (aliases A)
#define OFF_DV     66048    // Dinv block 16x17 floats = 1088 B
#define OFF_SQLP   67136
#define OFF_SMU    67648
#define OFF_UTLV   68160
#define OFF_DINV   68672
#define OFF_TF     69184
#define OFF_EPSV   69696
#define OFF_RED    70208
#define SMEM_DYN   70720

#define SB_STRIDE_B 144
#define P_STRIDE    129

__device__ __forceinline__ uint32_t s2u(const void* p) {
    uint32_t a;
    asm("{ .reg .u64 t; cvta.to.shared.u64 t, %1; cvt.u32.u64 %0, t; }"
        : "=r"(a) : "l"(p));
    return a;
}

__device__ __forceinline__ void ldsm_x4(uint32_t addr, uint32_t& r0, uint32_t& r1,
                                        uint32_t& r2, uint32_t& r3) {
    asm volatile("ldmatrix.sync.aligned.m8n8.x4.shared.b16 {%0,%1,%2,%3}, [%4];"
                 : "=r"(r0), "=r"(r1), "=r"(r2), "=r"(r3) : "r"(addr));
}

__device__ __forceinline__ void mma16816(float& c0, float& c1, float& c2, float& c3,
                                         uint32_t a0, uint32_t a1, uint32_t a2, uint32_t a3,
                                         uint32_t b0, uint32_t b1) {
    asm volatile(
        "mma.sync.aligned.m16n8k16.row.col.f32.bf16.bf16.f32 "
        "{%0,%1,%2,%3}, {%4,%5,%6,%7}, {%8,%9}, {%0,%1,%2,%3};"
        : "+f"(c0), "+f"(c1), "+f"(c2), "+f"(c3)
        : "r"(a0), "r"(a1), "r"(a2), "r"(a3), "r"(b0), "r"(b1));
}

__device__ __forceinline__ uint32_t pack_bf2(__nv_bfloat16 lo, __nv_bfloat16 hi) {
    uint16_t a = __bfloat16_as_ushort(lo), b = __bfloat16_as_ushort(hi);
    return (uint32_t)a | ((uint32_t)b << 16);
}
__device__ __forceinline__ uint32_t swap16(uint32_t x) {
    return __byte_perm(x, x, 0x1032);
}

// ---- 16x16 warp Cholesky (lanes 0..15 of calling warp) ----
__device__ __forceinline__ void chol16_warp(float* A, float* dinv) {
    const int lane = threadIdx.x & 31;
    if (lane < 16) {
        float row[16], rawv[16];
#pragma unroll
        for (int k = 0; k < 16; k++) row[k] = A[lane*PAD + k];
#pragma unroll
        for (int j = 0; j < 16; j++) {
            float raw = __shfl_sync(0xFFFFu, row[j], j);
            rawv[j] = raw;
            float inv = __fdividef(1.0f, raw);
            float tj = row[j] * inv;
#pragma unroll
            for (int k = j + 1; k < 16; k++) {
                float rkj = __shfl_sync(0xFFFFu, row[j], k);
                row[k] = fmaf(-tj, rkj, row[k]);
            }
        }
        float rs[16];
#pragma unroll
        for (int j = 0; j < 16; j++) rs[j] = rsqrtf(rawv[j]);
#pragma unroll
        for (int k = 0; k < 16; k++) {
            float v = (k < lane) ? row[k] * rs[k] : rawv[k] * rs[k];
            A[lane*PAD + k] = v;
        }
        dinv[lane] = rs[lane];
    }
    __syncwarp();
}

__device__ __noinline__ void chol_blocked(float* A, float* dinv, int tid) {
    const int warp = tid >> 5;
    const int ty = tid >> 4, tx = tid & 15;
#pragma unroll
    for (int jb = 0; jb < 8; jb++) {
        if (warp == 0) chol16_warp(A + (jb*16)*PAD + jb*16, dinv + jb*16);
        __syncthreads();
        const int nrows = 112 - jb*16;
        if (tid < nrows) {
            const int i = jb*16 + 16 + tid;
            const float* Ld = A + (jb*16)*PAD + jb*16;
            float* Ai = A + i*PAD + jb*16;
            float dv[16], t[16];
#pragma unroll
            for (int j = 0; j < 16; j++) dv[j] = dinv[jb*16 + j];
#pragma unroll
            for (int j = 0; j < 16; j++) t[j] = Ai[j];
#pragma unroll
            for (int j = 0; j < 16; j++) {
                float v = t[j] * dv[j];
                t[j] = v;
#pragma unroll
                for (int k = j + 1; k < 16; k++)
                    t[k] = fmaf(-v, Ld[k*PAD + j], t[k]);
            }
#pragma unroll
            for (int j = 0; j < 16; j++) Ai[j] = t[j];
        }
        __syncthreads();
        if (jb < 7) {
            float tacc[8][8];
#pragma unroll
            for (int a = jb+1; a < 8; a++)
#pragma unroll
                for (int b = jb+1; b <= a; b++) tacc[a][b] = 0.0f;
            float pa[8], pb[8];
#pragma unroll
            for (int k = 0; k < 16; k++) {
#pragma unroll
                for (int a = jb+1; a < 8; a++) pa[a] = A[(ty + 16*a)*PAD + jb*16 + k];
#pragma unroll
                for (int b = jb+1; b < 8; b++) pb[b] = A[(tx + 16*b)*PAD + jb*16 + k];
#pragma unroll
                for (int a = jb+1; a < 8; a++)
#pragma unroll
                    for (int b = jb+1; b <= a; b++) tacc[a][b] += pa[a] * pb[b];
            }
#pragma unroll
            for (int a = jb+1; a < 8; a++)
#pragma unroll
                for (int b = jb+1; b <= a; b++)
                    A[(ty + 16*a)*PAD + tx + 16*b] -= tacc[a][b];
            __syncthreads();
        }
    }
}

// Blocked X = L^{-1}, scratch-free in-place variant, race-free phase order:
//   phase1: Dinv (warp 7) + T accumulation entirely in registers (all L reads)
//   __syncthreads()  -> no L[ib][*] value is read after this point
//   phase2: store T into destination block, warp-fence, reload column,
//           warp-fence, multiply by Dinv, store X (per-warp-private block)
__device__ __noinline__ void trsm_blocked(float* A, const float* dinv,
                                          float* Dv, int tid) {
    const int warp = tid >> 5;
    const int lane = tid & 31;
    const int c = lane & 15, rh = lane >> 4;
#pragma unroll
    for (int ib = 0; ib < 8; ib++) {
        if (warp == 7 && lane < 16) {
            const float* Ld = A + (ib*16)*PAD + ib*16;
            float dv[16], t[16];
#pragma unroll
            for (int r = 0; r < 16; r++) dv[r] = dinv[ib*16 + r];
#pragma unroll
            for (int r = 0; r < 16; r++) t[r] = (r == c) ? 1.0f : 0.0f;
#pragma unroll
            for (int r = 0; r < 16; r++) {
                float x = t[r] * dv[r];
                t[r] = x;
#pragma unroll
                for (int k = r + 1; k < 16; k++)
                    t[k] = fmaf(-x, Ld[k*PAD + r], t[k]);
            }
#pragma unroll
            for (int r = 0; r < 16; r++) Dv[r*17 + c] = t[r];
        }
        float acc[8];
        if (warp < ib) {
#pragma unroll
            for (int q = 0; q < 8; q++) acc[q] = 0.0f;
            for (int kb = warp; kb < ib; kb++) {
#pragma unroll
                for (int k = 0; k < 16; k++) {
                    float xv = A[(kb*16 + k)*PAD + warp*16 + c];
#pragma unroll
                    for (int q = 0; q < 8; q++)
                        acc[q] -= A[(ib*16 + rh*8 + q)*PAD + kb*16 + k] * xv;
                }
            }
        }
        __syncthreads();   // ALL reads of L row ib complete; Dv visible
        if (warp < ib) {
#pragma unroll
            for (int q = 0; q < 8; q++)
                A[(ib*16 + rh*8 + q)*PAD + warp*16 + c] = acc[q];
            __syncwarp();
            float tcol[16];
#pragma unroll
            for (int k = 0; k < 16; k++)
                tcol[k] = A[(ib*16 + k)*PAD + warp*16 + c];
            __syncwarp();
#pragma unroll
            for (int q = 0; q < 8; q++) {
                const int r = rh*8 + q;
                float t = 0.0f;
#pragma unroll
                for (int k = 0; k <= r; k++)
                    t = fmaf(Dv[r*17 + k], tcol[k], t);
                A[(ib*16 + r)*PAD + warp*16 + c] = t;
            }
        }
        if (warp == 7 && lane < 16) {
#pragma unroll
            for (int r = 0; r < 16; r++)
                A[(ib*16 + r)*PAD + ib*16 + c] = Dv[r*17 + c];
        }
        __syncthreads();
    }
}

__global__ __launch_bounds__(256, 3)
void k1_factor(const float* __restrict__ U,
               const float* __restrict__ pmu,
               const float* __restrict__ plogprec,
               const float* __restrict__ eps) {
    extern __shared__ unsigned char smraw[];
    char* sm = (char*)smraw;
    const uint32_t smb = s2u(sm);

    float* A    = (float*)(sm + OFF_A);
    float* P    = (float*)(sm + OFF_P);
    float* Dv   = (float*)(sm + OFF_DV);
    float* sqlp = (float*)(sm + OFF_SQLP);
    float* smu  = (float*)(sm + OFF_SMU);
    float* utlv = (float*)(sm + OFF_UTLV);
    float* dinv = (float*)(sm + OFF_DINV);
    float* tf   = (float*)(sm + OFF_TF);
    float* epsv = (float*)(sm + OFF_EPSV);
    float* red  = (float*)(sm + OFF_RED);

    const int so = blockIdx.x;
    const int s = so >> 7;
    const int o = so & 127;
    const int tid = threadIdx.x;
    const int wid = tid >> 5;
    const int lane = tid & 31;

    if (tid < 128) {
        float l = expf(plogprec[o*MM + tid]);
        float sq = sqrtf(l);
        sqlp[tid] = sq;
        smu[tid]  = sq * pmu[o*MM + tid];
        epsv[tid] = eps[(s*OO + o)*DD + tid];
        utlv[tid] = 0.0f;
    }
    __syncthreads();

    // ---- tile lists: 72 lower tiles, 9/warp, static fill ----
    int rbv[9], jbv[9];
#pragma unroll
    for (int t = 0; t < 9; t++) {
        int idx = wid + 8*t;
        int rb = (int)(0.5f * (sqrtf(4.0f*(float)idx + 1.0f) - 1.0f));
        if (rb*rb + rb > idx) rb--;
        if ((rb+1)*(rb+1) + (rb+1) <= idx) rb++;
        rbv[t] = rb;
        jbv[t] = idx - rb*rb - rb;
    }
    const int aRow  = lane & 15;
    const int aColH = (lane >> 4) * 8;
    const int bRow  = lane & 7;
    const int bCol  = (lane >> 3) * 8;

    float cc[9][4];
#pragma unroll
    for (int t = 0; t < 9; t++)
#pragma unroll
        for (int q = 0; q < 4; q++) cc[t][q] = 0.f;

    const int pfd = tid & 127;
    const int pfm = tid >> 7;

    // ============ Gram = P~^T P~  (32-m chunks; SB0/P alias A) ============
#pragma unroll
    for (int c = 0; c < 4; c++) {
#pragma unroll
        for (int it = 0; it < 16; it++) {
            int ml = pfm + 2*it;
            float u = U[((size_t)s*MM + c*32 + ml)*DD + pfd];
            P[ml*P_STRIDE + pfd] = sqlp[c*32 + ml] * fmaxf(u, 0.f);
        }
        __syncthreads();
        if (tid < 128) {
            float a = utlv[tid];
#pragma unroll
            for (int ml = 0; ml < 32; ml++)
                a = fmaf(smu[c*32 + ml], P[ml*P_STRIDE + tid], a);
            utlv[tid] = a;
        }
#pragma unroll
        for (int it = 0; it < 16; it++) {
            int idx = tid + it*256;
            int ml = idx & 31, d = idx >> 5;
            float v = P[ml*P_STRIDE + d];
            __nv_bfloat16 h = __float2bfloat16(v);
            __nv_bfloat16 m2 = __float2bfloat16(v - __bfloat162float(h));
            *(uint32_t*)(sm + OFF_SB0 + d*SB_STRIDE_B + ml*4) = pack_bf2(h, m2);
        }
        __syncthreads();
#pragma unroll
        for (int t = 0; t < 9; t++) {
            uint32_t aBase = smb + OFF_SB0 + (uint32_t)(rbv[t]*16 + aRow)*SB_STRIDE_B + aColH*2;
            uint32_t bBase = smb + OFF_SB0 + (uint32_t)(jbv[t]*8 + bRow)*SB_STRIDE_B + bCol*2;
#pragma unroll
            for (int g = 0; g < 2; g++) {
                uint32_t b0,b1,b2,b3;
                ldsm_x4(bBase + g*64, b0,b1,b2,b3);
                uint32_t s0 = swap16(b0), s1 = swap16(b1), s2 = swap16(b2), s3 = swap16(b3);
                uint32_t a0,a1,a2,a3;
                ldsm_x4(aBase + (2*g)*32, a0,a1,a2,a3);
                mma16816(cc[t][0],cc[t][1],cc[t][2],cc[t][3], a0,a1,a2,a3, b0,b1);
                mma16816(cc[t][0],cc[t][1],cc[t][2],cc[t][3], a0,a1,a2,a3, s0,s1);
                ldsm_x4(aBase + (2*g+1)*32, a0,a1,a2,a3);
                mma16816(cc[t][0],cc[t][1],cc[t][2],cc[t][3], a0,a1,a2,a3, b2,b3);
                mma16816(cc[t][0],cc[t][1],cc[t][2],cc[t][3], a0,a1,a2,a3, s2,s3);
            }
        }
        __syncthreads();
    }
    // store Gram + I, FLIPPED: Af[127-j][127-i] = G[i][j]
    {
        const int g = lane >> 2, tc = (lane & 3) * 2;
#pragma unroll
        for (int t = 0; t < 9; t++) {
            int i0 = rbv[t]*16 + g, j0 = jbv[t]*8 + tc;
            A[(127-j0)*PAD + (127-i0)]     = cc[t][0] + (i0 == j0     ? 1.f : 0.f);
            A[(127-j0-1)*PAD + (127-i0)]   = cc[t][1] + (i0 == j0 + 1 ? 1.f : 0.f);
            A[(127-j0)*PAD + (127-i0-8)]   = cc[t][2] + (i0+8 == j0   ? 1.f : 0.f);
            A[(127-j0-1)*PAD + (127-i0-8)] = cc[t][3] + (i0+8 == j0+1 ? 1.f : 0.f);
        }
    }
    __syncthreads();

    // ---- Lf = chol(Af); Xf = Lf^{-1} ----
    chol_blocked(A, dinv, tid);
    trsm_blocked(A, dinv, Dv, tid);

    // ---- tf = Xf @ flip(utlv) ----
    if (tid < 128) {
        const float* Ar = A + tid*PAD;
        float a = 0.f;
        for (int e = 0; e <= tid; e++)
            a = fmaf(Ar[e], utlv[127 - e], a);
        tf[tid] = a;
    }
    __syncthreads();

    // ---- column dots over column c=127-i: q_mu, Lcov@eps, colnorm ----
    if (tid < 128) {
        const int c = 127 - tid;
        float qm = 0.f, we = 0.f, ss = 0.f;
        for (int k = (c & ~15); k < 128; k++) {
            float x = A[k*PAD + c];
            qm = fmaf(x, tf[k], qm);
            we = fmaf(x, epsv[127 - k], we);
            ss = fmaf(x, x, ss);
        }
        g_w[(s*OO + o)*DD + tid] = qm + we;
        red[tid] = 0.5f*(ss + qm*qm) - logf(dinv[tid]);
    }
    __syncthreads();
    if (tid < 32) {
        float p = red[tid] + red[tid+32] + red[tid+64] + red[tid+96];
#pragma unroll
        for (int off = 16; off > 0; off >>= 1)
            p += __shfl_xor_sync(0xFFFFFFFFu, p, off);
        if (tid == 0)
            g_klso[so] = p - 64.0f;
    }
}

// ---- k2: F_out / U_out GEMMs, float4-over-k ----
#define KP 36
__global__ __launch_bounds__(256, 2)
void k2_gemm(const float* __restrict__ F, const float* __restrict__ U,
             float* __restrict__ outF, float* __restrict__ outU) {
    __shared__ float At[128*KP];
    __shared__ float Bt[128*KP];
    const int b = blockIdx.x;
    const int tid = threadIdx.x;
    const int ty = tid >> 4, tx = tid & 15;

    int s;
    const float* Ag;
    float* Cg;
    if (b < SS * (NN/128)) {
        s = b >> 5;
        int nt = b & 31;
        Ag = F + (size_t)(s*NN + nt*128) * DD;
        Cg = outF + (size_t)(s*NN + nt*128) * OO;
    } else {
        s = b - SS * (NN/128);
        Ag = U + (size_t)(s*MM) * DD;
        Cg = outU + (size_t)(s*MM) * OO;
    }
    const float* W = g_w + (size_t)s * OO * DD;

    float acc[8][8];
#pragma unroll
    for (int a = 0; a < 8; a++)
#pragma unroll
        for (int c = 0; c < 8; c++) acc[a][c] = 0.0f;

    for (int kb = 0; kb < DD; kb += 32) {
        __syncthreads();
        for (int idx = tid; idx < 128*8; idx += 256) {
            int r = idx >> 3, c4 = idx & 7;
            float4 v = *(const float4*)&Ag[r*DD + kb + 4*c4];
            v.x = fmaxf(v.x, 0.f); v.y = fmaxf(v.y, 0.f);
            v.z = fmaxf(v.z, 0.f); v.w = fmaxf(v.w, 0.f);
            *(float4*)&At[r*KP + 4*c4] = v;
            *(float4*)&Bt[r*KP + 4*c4] = *(const float4*)&W[r*DD + kb + 4*c4];
        }
        __syncthreads();
#pragma unroll
        for (int k4 = 0; k4 < 8; k4++) {
            float4 bv[8];
#pragma unroll
            for (int c = 0; c < 8; c++)
                bv[c] = *(const float4*)&Bt[(tx + 16*c)*KP + 4*k4];
#pragma unroll
            for (int a = 0; a < 8; a++) {
                float4 av = *(const float4*)&At[(ty + 16*a)*KP + 4*k4];
#pragma unroll
                for (int c = 0; c < 8; c++) {
                    acc[a][c] += av.x * bv[c].x;
                    acc[a][c] += av.y * bv[c].y;
                    acc[a][c] += av.z * bv[c].z;
                    acc[a][c] += av.w * bv[c].w;
                }
            }
        }
    }
#pragma unroll
    for (int a = 0; a < 8; a++)
#pragma unroll
        for (int c = 0; c < 8; c++)
            Cg[(ty + 16*a)*OO + tx + 16*c] = acc[a][c];
}

__global__ void k3_kl(float* __restrict__ kl) {
    int s = threadIdx.x;
    if (s < SS) {
        float a = 0.0f;
        for (int o = 0; o < OO; o++) a += g_klso[s*OO + o];
        kl[s] = a;
    }
}

extern "C" void kernel_launch(void* const* d_in, const int* in_sizes, int n_in,
                              void* d_out, int out_size) {
    const float* F        = (const float*)d_in[0];
    const float* U        = (const float*)d_in[1];
    const float* pmu      = (const float*)d_in[2];
    const float* plogprec = (const float*)d_in[3];
    const float* eps      = (const float*)d_in[4];

    float* out  = (float*)d_out;
    float* outF = out;
    float* outU = outF + (size_t)SS*NN*OO;
    float* outK = outU + (size_t)SS*MM*OO;

    cudaFuncSetAttribute(k1_factor, cudaFuncAttributeMaxDynamicSharedMemorySize,
                         SMEM_DYN);

    k1_factor<<<SS*OO, 256, SMEM_DYN>>>(U, pmu, plogprec, eps);
    k2_gemm<<<SS*(NN/128) + SS, 256>>>(F, U, outF, outU);
    k3_kl<<<1, 32>>>(outK);
}